// round 1
// baseline (speedup 1.0000x reference)
#include <cuda_runtime.h>
#include <math.h>

// Problem constants
#define CIN   64
#define HW    56
#define LL    3136        // 56*56
#define COUT  128
#define DD    576         // 64*3*3
#define MM    100352      // 32*3136
#define BK    16

// Pre-transposed weights: Wt[d][n]  (d = Cin*3*3, n = Cout)
__device__ float g_Wt[DD * COUT];

__global__ void transpose_w_kernel(const float* __restrict__ W) {
    int idx = blockIdx.x * 256 + threadIdx.x;
    if (idx < DD * COUT) {
        int n = idx / DD;
        int d = idx - n * DD;
        g_Wt[d * COUT + n] = W[idx];
    }
}

__global__ __launch_bounds__(256, 2)
void logic_conv_kernel(const float* __restrict__ x,
                       const float* __restrict__ bias,
                       float* __restrict__ out) {
    __shared__ float As[2][BK][128];
    __shared__ float Bs[2][BK][128];

    const int t  = threadIdx.x;
    const int bm = blockIdx.x * 128;

    // ---- A loader indices (im2col on the fly) ----
    const int mA = t & 127;          // row within tile
    const int kA = (t >> 7) * 8;     // 0 or 8 : this thread loads k = kA..kA+7
    const int gm   = bm + mA;
    const int bimg = gm / LL;
    const int l    = gm - bimg * LL;
    const int y    = l / HW;
    const int xx   = l - y * HW;
    const long xbase = (long)bimg * (CIN * LL) + y * HW + xx - (HW + 1);

    // ---- B loader indices ----
    const int nB = t & 127;          // col
    const int kB = (t >> 7);         // 0 or 1 : rows kB + 2*kk

    // ---- compute thread mapping (16x16 thread grid, 8x8 micro tile) ----
    const int tx = t & 15;
    const int ty = t >> 4;

    float acc[8][8];
    #pragma unroll
    for (int i = 0; i < 8; i++)
        #pragma unroll
        for (int j = 0; j < 8; j++) acc[i][j] = 0.f;

    float aReg[8], bReg[8];

    // ---- prologue: fetch chunk 0 into regs, store to smem buf 0 ----
    #pragma unroll
    for (int kk = 0; kk < 8; kk++) {
        int d = kA + kk;
        int c = d / 9; int r = d - c * 9;
        int i = r / 3; int j = r - i * 3;
        bool valid = ((unsigned)(y + i - 1) < HW) && ((unsigned)(xx + j - 1) < HW);
        aReg[kk] = valid ? __ldg(&x[xbase + c * LL + i * HW + j]) : 0.f;
    }
    #pragma unroll
    for (int kk = 0; kk < 8; kk++)
        bReg[kk] = g_Wt[(kB + kk * 2) * COUT + nB];

    #pragma unroll
    for (int kk = 0; kk < 8; kk++) As[0][kA + kk][mA] = aReg[kk];
    #pragma unroll
    for (int kk = 0; kk < 8; kk++) Bs[0][kB + kk * 2][nB] = bReg[kk];
    __syncthreads();

    const int NCHUNK = DD / BK;   // 36
    for (int chunk = 0; chunk < NCHUNK; chunk++) {
        const int buf = chunk & 1;

        // issue global loads for next chunk early (hide latency under compute)
        if (chunk + 1 < NCHUNK) {
            const int kc = (chunk + 1) * BK;
            #pragma unroll
            for (int kk = 0; kk < 8; kk++) {
                int d = kc + kA + kk;
                int c = d / 9; int r = d - c * 9;
                int i = r / 3; int j = r - i * 3;
                bool valid = ((unsigned)(y + i - 1) < HW) && ((unsigned)(xx + j - 1) < HW);
                aReg[kk] = valid ? __ldg(&x[xbase + c * LL + i * HW + j]) : 0.f;
            }
            #pragma unroll
            for (int kk = 0; kk < 8; kk++)
                bReg[kk] = g_Wt[(kc + kB + kk * 2) * COUT + nB];
        }

        // compute on current buffer
        #pragma unroll
        for (int kk = 0; kk < BK; kk++) {
            float4 a0 = *(const float4*)&As[buf][kk][tx * 4];
            float4 a1 = *(const float4*)&As[buf][kk][tx * 4 + 64];
            float4 b0 = *(const float4*)&Bs[buf][kk][ty * 4];
            float4 b1 = *(const float4*)&Bs[buf][kk][ty * 4 + 64];
            float a[8] = {a0.x, a0.y, a0.z, a0.w, a1.x, a1.y, a1.z, a1.w};
            float b[8] = {b0.x, b0.y, b0.z, b0.w, b1.x, b1.y, b1.z, b1.w};
            #pragma unroll
            for (int i = 0; i < 8; i++)
                #pragma unroll
                for (int j = 0; j < 8; j++)
                    acc[i][j] = fmaf(a[i], b[j], acc[i][j]);
        }

        // stage next chunk into the other buffer (safe: nobody reads it yet)
        if (chunk + 1 < NCHUNK) {
            const int nbuf = buf ^ 1;
            #pragma unroll
            for (int kk = 0; kk < 8; kk++) As[nbuf][kA + kk][mA] = aReg[kk];
            #pragma unroll
            for (int kk = 0; kk < 8; kk++) Bs[nbuf][kB + kk * 2][nB] = bReg[kk];
            __syncthreads();
        }
    }

    // ---- epilogue: z = acc + bias ; out = (sin(z)^2 > 0.5) ? 1 : 0 ----
    #pragma unroll
    for (int mh = 0; mh < 2; mh++) {
        const int m0    = mh * 64 + tx * 4;
        const int gm0   = bm + m0;
        const int b0img = gm0 / LL;       // constant across the 4 consecutive m
        const int l0    = gm0 - b0img * LL;
        #pragma unroll
        for (int nh = 0; nh < 2; nh++) {
            #pragma unroll
            for (int nj = 0; nj < 4; nj++) {
                const int n = nh * 64 + ty * 4 + nj;
                const float bv = __ldg(&bias[n]);
                float4 o;
                float* po = (float*)&o;
                #pragma unroll
                for (int mi = 0; mi < 4; mi++) {
                    float z = acc[mh * 4 + mi][nh * 4 + nj] + bv;
                    float s = sinf(z);
                    po[mi] = (s * s > 0.5f) ? 1.f : 0.f;
                }
                *(float4*)&out[((long)b0img * COUT + n) * LL + l0] = o;
            }
        }
    }
}

extern "C" void kernel_launch(void* const* d_in, const int* in_sizes, int n_in,
                              void* d_out, int out_size) {
    const float* x = (const float*)d_in[0];   // (32, 64, 56, 56)
    const float* W = (const float*)d_in[1];   // (128, 576)
    const float* b = (const float*)d_in[2];   // (128,)
    float* out = (float*)d_out;               // (32, 128, 56, 56)

    transpose_w_kernel<<<(DD * COUT + 255) / 256, 256>>>(W);
    logic_conv_kernel<<<MM / 128, 256>>>(x, b, out);
}

// round 2
// speedup vs baseline: 1.0030x; 1.0030x over previous
#include <cuda_runtime.h>
#include <math.h>

// Problem constants
#define CIN   64
#define HW    56
#define LL    3136        // 56*56
#define COUT  128
#define DD    576         // 64*3*3
#define MM    100352      // 32*3136
#define BK    16

// Pre-transposed weights: Wt[d][n]  (d = Cin*3*3, n = Cout)
__device__ float g_Wt[DD * COUT];

__global__ void transpose_w_kernel(const float* __restrict__ W) {
    int idx = blockIdx.x * 256 + threadIdx.x;
    if (idx < DD * COUT) {
        int n = idx / DD;
        int d = idx - n * DD;
        g_Wt[d * COUT + n] = W[idx];
    }
}

__global__ __launch_bounds__(256, 2)
void logic_conv_kernel(const float* __restrict__ x,
                       const float* __restrict__ bias,
                       float* __restrict__ out) {
    __shared__ float As[2][BK][128];
    __shared__ float Bs[2][BK][128];

    const int t  = threadIdx.x;
    const int bm = blockIdx.x * 128;

    // ---- A loader indices (im2col on the fly) ----
    const int mA = t & 127;          // row within tile
    const int kA = (t >> 7) * 8;     // 0 or 8 : this thread loads k = kA..kA+7
    const int gm   = bm + mA;
    const int bimg = gm / LL;
    const int l    = gm - bimg * LL;
    const int y    = l / HW;
    const int xx   = l - y * HW;
    const long xbase = (long)bimg * (CIN * LL) + y * HW + xx - (HW + 1);

    // ---- B loader indices ----
    const int nB = t & 127;          // col
    const int kB = (t >> 7);         // 0 or 1 : rows kB + 2*kk

    // ---- compute thread mapping (16x16 thread grid, 8x8 micro tile) ----
    const int tx = t & 15;
    const int ty = t >> 4;

    float acc[8][8];
    #pragma unroll
    for (int i = 0; i < 8; i++)
        #pragma unroll
        for (int j = 0; j < 8; j++) acc[i][j] = 0.f;

    float aReg[8], bReg[8];

    // ---- prologue: fetch chunk 0 into regs, store to smem buf 0 ----
    #pragma unroll
    for (int kk = 0; kk < 8; kk++) {
        int d = kA + kk;
        int c = d / 9; int r = d - c * 9;
        int i = r / 3; int j = r - i * 3;
        bool valid = ((unsigned)(y + i - 1) < HW) && ((unsigned)(xx + j - 1) < HW);
        aReg[kk] = valid ? __ldg(&x[xbase + c * LL + i * HW + j]) : 0.f;
    }
    #pragma unroll
    for (int kk = 0; kk < 8; kk++)
        bReg[kk] = g_Wt[(kB + kk * 2) * COUT + nB];

    #pragma unroll
    for (int kk = 0; kk < 8; kk++) As[0][kA + kk][mA] = aReg[kk];
    #pragma unroll
    for (int kk = 0; kk < 8; kk++) Bs[0][kB + kk * 2][nB] = bReg[kk];
    __syncthreads();

    const int NCHUNK = DD / BK;   // 36
    for (int chunk = 0; chunk < NCHUNK; chunk++) {
        const int buf = chunk & 1;

        // issue global loads for next chunk early (hide latency under compute)
        if (chunk + 1 < NCHUNK) {
            const int kc = (chunk + 1) * BK;
            #pragma unroll
            for (int kk = 0; kk < 8; kk++) {
                int d = kc + kA + kk;
                int c = d / 9; int r = d - c * 9;
                int i = r / 3; int j = r - i * 3;
                bool valid = ((unsigned)(y + i - 1) < HW) && ((unsigned)(xx + j - 1) < HW);
                aReg[kk] = valid ? __ldg(&x[xbase + c * LL + i * HW + j]) : 0.f;
            }
            #pragma unroll
            for (int kk = 0; kk < 8; kk++)
                bReg[kk] = g_Wt[(kc + kB + kk * 2) * COUT + nB];
        }

        // compute on current buffer
        #pragma unroll
        for (int kk = 0; kk < BK; kk++) {
            float4 a0 = *(const float4*)&As[buf][kk][tx * 4];
            float4 a1 = *(const float4*)&As[buf][kk][tx * 4 + 64];
            float4 b0 = *(const float4*)&Bs[buf][kk][ty * 4];
            float4 b1 = *(const float4*)&Bs[buf][kk][ty * 4 + 64];
            float a[8] = {a0.x, a0.y, a0.z, a0.w, a1.x, a1.y, a1.z, a1.w};
            float b[8] = {b0.x, b0.y, b0.z, b0.w, b1.x, b1.y, b1.z, b1.w};
            #pragma unroll
            for (int i = 0; i < 8; i++)
                #pragma unroll
                for (int j = 0; j < 8; j++)
                    acc[i][j] = fmaf(a[i], b[j], acc[i][j]);
        }

        // stage next chunk into the other buffer (safe: nobody reads it yet)
        if (chunk + 1 < NCHUNK) {
            const int nbuf = buf ^ 1;
            #pragma unroll
            for (int kk = 0; kk < 8; kk++) As[nbuf][kA + kk][mA] = aReg[kk];
            #pragma unroll
            for (int kk = 0; kk < 8; kk++) Bs[nbuf][kB + kk * 2][nB] = bReg[kk];
            __syncthreads();
        }
    }

    // ---- epilogue: z = acc + bias ; out = (sin(z)^2 > 0.5) ? 1 : 0 ----
    #pragma unroll
    for (int mh = 0; mh < 2; mh++) {
        const int m0    = mh * 64 + tx * 4;
        const int gm0   = bm + m0;
        const int b0img = gm0 / LL;       // constant across the 4 consecutive m
        const int l0    = gm0 - b0img * LL;
        #pragma unroll
        for (int nh = 0; nh < 2; nh++) {
            #pragma unroll
            for (int nj = 0; nj < 4; nj++) {
                const int n = nh * 64 + ty * 4 + nj;
                const float bv = __ldg(&bias[n]);
                float4 o;
                float* po = (float*)&o;
                #pragma unroll
                for (int mi = 0; mi < 4; mi++) {
                    float z = acc[mh * 4 + mi][nh * 4 + nj] + bv;
                    float s = sinf(z);
                    po[mi] = (s * s > 0.5f) ? 1.f : 0.f;
                }
                *(float4*)&out[((long)b0img * COUT + n) * LL + l0] = o;
            }
        }
    }
}

extern "C" void kernel_launch(void* const* d_in, const int* in_sizes, int n_in,
                              void* d_out, int out_size) {
    const float* x = (const float*)d_in[0];   // (32, 64, 56, 56)
    const float* W = (const float*)d_in[1];   // (128, 576)
    const float* b = (const float*)d_in[2];   // (128,)
    float* out = (float*)d_out;               // (32, 128, 56, 56)

    transpose_w_kernel<<<(DD * COUT + 255) / 256, 256>>>(W);
    logic_conv_kernel<<<MM / 128, 256>>>(x, b, out);
}

// round 3
// speedup vs baseline: 1.0381x; 1.0350x over previous
#include <cuda_runtime.h>
#include <math.h>

// Problem constants
#define CIN   64
#define HW    56
#define LL    3136        // 56*56
#define COUT  128
#define DD    576         // 64*3*3
#define MM    100352      // 32*3136
#define BK    16

#define INV_PI 0.3183098861837907f

// Pre-transposed weights: Wt[d][n]  (d = Cin*3*3, n = Cout)
__device__ float g_Wt[DD * COUT];

__global__ void transpose_w_kernel(const float* __restrict__ W) {
    int idx = blockIdx.x * 256 + threadIdx.x;
    if (idx < DD * COUT) {
        int n = idx / DD;
        int d = idx - n * DD;
        g_Wt[d * COUT + n] = W[idx];
    }
}

// ---- packed f32x2 helpers (sm_103a) ----
__device__ __forceinline__ unsigned long long pack_dup(float v) {
    unsigned long long r;
    asm("mov.b64 %0, {%1, %1};" : "=l"(r) : "f"(v));
    return r;
}
__device__ __forceinline__ void ffma2(unsigned long long &acc,
                                      unsigned long long a,
                                      unsigned long long b) {
    asm("fma.rn.f32x2 %0, %1, %2, %0;" : "+l"(acc) : "l"(a), "l"(b));
}
__device__ __forceinline__ float2 unpack2(unsigned long long v) {
    float2 r;
    asm("mov.b64 {%0, %1}, %2;" : "=f"(r.x), "=f"(r.y) : "l"(v));
    return r;
}

union F4U2 { float4 f; unsigned long long u[2]; };

__global__ __launch_bounds__(256, 2)
void logic_conv_kernel(const float* __restrict__ x,
                       const float* __restrict__ bias,
                       float* __restrict__ out) {
    __shared__ __align__(16) float As[2][BK][128];
    __shared__ __align__(16) float Bs[2][BK][128];

    const int t  = threadIdx.x;
    const int bm = blockIdx.x * 128;

    // ---- A loader indices (im2col on the fly) ----
    const int mA = t & 127;          // row within tile
    const int kA = (t >> 7) * 8;     // 0 or 8 : this thread loads k = kA..kA+7
    const int gm   = bm + mA;
    const int bimg = gm / LL;
    const int l    = gm - bimg * LL;
    const int y    = l / HW;
    const int xx   = l - y * HW;
    const long xbase = (long)bimg * (CIN * LL) + y * HW + xx - (HW + 1);

    // ---- B loader indices ----
    const int nB = t & 127;          // col
    const int kB = (t >> 7);         // 0 or 1 : rows kB + 2*kk

    // ---- compute thread mapping (16x16 thread grid, 8x8 micro tile) ----
    const int tx = t & 15;
    const int ty = t >> 4;

    // packed accumulators: acc2[i][j] holds m-pair (2i,2i+1) x n column j
    unsigned long long acc2[4][8];
    #pragma unroll
    for (int i = 0; i < 4; i++)
        #pragma unroll
        for (int j = 0; j < 8; j++) acc2[i][j] = 0ULL;

    float aReg[8], bReg[8];

    // ---- prologue: fetch chunk 0 into regs, store to smem buf 0 ----
    #pragma unroll
    for (int kk = 0; kk < 8; kk++) {
        int d = kA + kk;
        int c = d / 9; int r = d - c * 9;
        int i = r / 3; int j = r - i * 3;
        bool valid = ((unsigned)(y + i - 1) < HW) && ((unsigned)(xx + j - 1) < HW);
        aReg[kk] = valid ? __ldg(&x[xbase + c * LL + i * HW + j]) : 0.f;
    }
    #pragma unroll
    for (int kk = 0; kk < 8; kk++)
        bReg[kk] = g_Wt[(kB + kk * 2) * COUT + nB];

    #pragma unroll
    for (int kk = 0; kk < 8; kk++) As[0][kA + kk][mA] = aReg[kk];
    #pragma unroll
    for (int kk = 0; kk < 8; kk++) Bs[0][kB + kk * 2][nB] = bReg[kk];
    __syncthreads();

    const int NCHUNK = DD / BK;   // 36
    for (int chunk = 0; chunk < NCHUNK; chunk++) {
        const int buf = chunk & 1;

        // issue global loads for next chunk early (hide latency under compute)
        if (chunk + 1 < NCHUNK) {
            const int kc = (chunk + 1) * BK;
            #pragma unroll
            for (int kk = 0; kk < 8; kk++) {
                int d = kc + kA + kk;
                int c = d / 9; int r = d - c * 9;
                int i = r / 3; int j = r - i * 3;
                bool valid = ((unsigned)(y + i - 1) < HW) && ((unsigned)(xx + j - 1) < HW);
                aReg[kk] = valid ? __ldg(&x[xbase + c * LL + i * HW + j]) : 0.f;
            }
            #pragma unroll
            for (int kk = 0; kk < 8; kk++)
                bReg[kk] = g_Wt[(kc + kB + kk * 2) * COUT + nB];
        }

        // compute on current buffer (packed f32x2 FMA)
        #pragma unroll
        for (int kk = 0; kk < BK; kk++) {
            F4U2 a0u, a1u;
            a0u.f = *(const float4*)&As[buf][kk][tx * 4];
            a1u.f = *(const float4*)&As[buf][kk][tx * 4 + 64];
            float4 b0 = *(const float4*)&Bs[buf][kk][ty * 4];
            float4 b1 = *(const float4*)&Bs[buf][kk][ty * 4 + 64];
            unsigned long long a2[4] = {a0u.u[0], a0u.u[1], a1u.u[0], a1u.u[1]};
            float b[8] = {b0.x, b0.y, b0.z, b0.w, b1.x, b1.y, b1.z, b1.w};
            #pragma unroll
            for (int j = 0; j < 8; j++) {
                unsigned long long bb = pack_dup(b[j]);
                #pragma unroll
                for (int i = 0; i < 4; i++)
                    ffma2(acc2[i][j], a2[i], bb);
            }
        }

        // stage next chunk into the other buffer
        if (chunk + 1 < NCHUNK) {
            const int nbuf = buf ^ 1;
            #pragma unroll
            for (int kk = 0; kk < 8; kk++) As[nbuf][kA + kk][mA] = aReg[kk];
            #pragma unroll
            for (int kk = 0; kk < 8; kk++) Bs[nbuf][kB + kk * 2][nB] = bReg[kk];
            __syncthreads();
        }
    }

    // ---- epilogue ----
    // sin^2(z) > 0.5  <=>  cos(2z) < 0  <=>  frac(z/pi - 1/4) < 1/2
    // fold bias: u = acc/pi + (bias/pi - 1/4)
    float ub[8];
    #pragma unroll
    for (int j = 0; j < 8; j++) {
        int n = (j < 4) ? (ty * 4 + j) : (64 + ty * 4 + (j - 4));
        ub[j] = fmaf(__ldg(&bias[n]), INV_PI, -0.25f);
    }

    #pragma unroll
    for (int mh = 0; mh < 2; mh++) {
        const int m0    = mh * 64 + tx * 4;
        const int gm0   = bm + m0;
        const int b0img = gm0 / LL;        // constant across the 4 consecutive m
        const int l0    = gm0 - b0img * LL;
        #pragma unroll
        for (int j = 0; j < 8; j++) {
            const int n = (j < 4) ? (ty * 4 + j) : (64 + ty * 4 + (j - 4));
            float2 p0 = unpack2(acc2[mh * 2 + 0][j]);
            float2 p1 = unpack2(acc2[mh * 2 + 1][j]);
            float zs[4] = {p0.x, p0.y, p1.x, p1.y};
            float4 o;
            float* po = (float*)&o;
            #pragma unroll
            for (int mi = 0; mi < 4; mi++) {
                float u = fmaf(zs[mi], INV_PI, ub[j]);
                float f = u - floorf(u);
                po[mi] = (f < 0.5f) ? 1.f : 0.f;
            }
            *(float4*)&out[((long)b0img * COUT + n) * LL + l0] = o;
        }
    }
}

extern "C" void kernel_launch(void* const* d_in, const int* in_sizes, int n_in,
                              void* d_out, int out_size) {
    const float* x = (const float*)d_in[0];   // (32, 64, 56, 56)
    const float* W = (const float*)d_in[1];   // (128, 576)
    const float* b = (const float*)d_in[2];   // (128,)
    float* out = (float*)d_out;               // (32, 128, 56, 56)

    transpose_w_kernel<<<(DD * COUT + 255) / 256, 256>>>(W);
    logic_conv_kernel<<<MM / 128, 256>>>(x, b, out);
}

// round 6
// speedup vs baseline: 1.1855x; 1.1421x over previous
#include <cuda_runtime.h>
#include <cuda_bf16.h>
#include <stdint.h>
#include <math.h>

// Problem constants
#define CIN    64
#define HWD    56
#define LL     3136
#define COUT   128
#define MM     100352
#define DD     576
#define BM     128
#define BK     64
#define NCHUNK 9
#define THREADS 384          // warps 0-7 consumers, 8-11 producers
#define INV_PI 0.3183098861837907f

// 3-way bf16 split of W, [COUT][DD] (k-contiguous = exactly what ldmatrix B wants)
__device__ __nv_bfloat16 g_Wh[COUT*DD];
__device__ __nv_bfloat16 g_Wm[COUT*DD];
__device__ __nv_bfloat16 g_Wl[COUT*DD];

__global__ void split_w_kernel(const float* __restrict__ W) {
    int i = blockIdx.x * 256 + threadIdx.x;
    if (i < COUT * DD) {
        float v = W[i];
        __nv_bfloat16 h = __float2bfloat16(v);
        float r1 = v - __bfloat162float(h);
        __nv_bfloat16 m = __float2bfloat16(r1);
        float r2 = r1 - __bfloat162float(m);
        g_Wh[i] = h; g_Wm[i] = m; g_Wl[i] = __float2bfloat16(r2);
    }
}

// ---------------- PTX helpers ----------------
__device__ __forceinline__ uint32_t smem_u32(const void* p) {
    uint32_t a;
    asm("{ .reg .u64 t; cvta.to.shared.u64 t, %1; cvt.u32.u64 %0, t; }" : "=r"(a) : "l"(p));
    return a;
}
#define MBAR_INIT(a, n) asm volatile("mbarrier.init.shared.b64 [%0], %1;" :: "r"(a), "r"(n) : "memory")
#define MBAR_ARRIVE(a)  asm volatile("mbarrier.arrive.shared.b64 _, [%0];" :: "r"(a) : "memory")
#define MBAR_WAIT(a, ph) do { \
    uint32_t _m = (a); uint32_t _p = (ph); uint32_t _d; \
    asm volatile("{\n\t.reg .pred p;\n\t" \
        "mbarrier.try_wait.parity.acquire.cta.shared::cta.b64 p, [%1], %2;\n\t" \
        "selp.b32 %0, 1, 0, p;\n\t}" : "=r"(_d) : "r"(_m), "r"(_p) : "memory"); \
    if (!_d) { \
        asm volatile("{\n\t.reg .pred P1;\n\t" \
            "WL_%=:\n\t" \
            "mbarrier.try_wait.parity.acquire.cta.shared::cta.b64 P1, [%0], %1, 0x989680;\n\t" \
            "@P1 bra.uni WD_%=;\n\t" \
            "bra.uni WL_%=;\n\t" \
            "WD_%=:\n\t}" :: "r"(_m), "r"(_p) : "memory"); \
    } } while (0)

#define STS128(a, v) asm volatile("st.shared.v4.b32 [%0], {%1,%2,%3,%4};" \
    :: "r"(a), "r"((v).x), "r"((v).y), "r"((v).z), "r"((v).w) : "memory")

#define LDSM4(r, a) asm volatile( \
    "ldmatrix.sync.aligned.m8n8.x4.shared.b16 {%0,%1,%2,%3}, [%4];" \
    : "=r"((r)[0]), "=r"((r)[1]), "=r"((r)[2]), "=r"((r)[3]) : "r"(a))

#define MMA(cc, a, b0_, b1_) asm volatile( \
    "mma.sync.aligned.m16n8k16.row.col.f32.bf16.bf16.f32 " \
    "{%0,%1,%2,%3},{%4,%5,%6,%7},{%8,%9},{%0,%1,%2,%3};" \
    : "+f"((cc)[0]), "+f"((cc)[1]), "+f"((cc)[2]), "+f"((cc)[3]) \
    : "r"((a)[0]), "r"((a)[1]), "r"((a)[2]), "r"((a)[3]), "r"(b0_), "r"(b1_))

// smem stage: 6 tiles (Ah Am Al Bh Bm Bl), each [128 rows][64 bf16 = 128B] swizzled
#define TILE_B  16384
#define STAGE_B (6 * TILE_B)
#define SMEM_DYN (2 * STAGE_B)

__global__ __launch_bounds__(THREADS, 1)
void conv_mma_kernel(const float* __restrict__ x,
                     const float* __restrict__ bias,
                     float* __restrict__ out) {
    extern __shared__ char dsm[];
    __shared__ __align__(8) unsigned long long s_bar[4]; // full0 full1 empty0 empty1
    __shared__ int   s_tab[DD];
    __shared__ float s_ub[COUT];

    const uint32_t sbase = smem_u32(dsm);
    const uint32_t bar_full[2]  = { smem_u32(&s_bar[0]), smem_u32(&s_bar[1]) };
    const uint32_t bar_empty[2] = { smem_u32(&s_bar[2]), smem_u32(&s_bar[3]) };

    const int t   = threadIdx.x;
    const int wid = t >> 5;
    const int lid = t & 31;
    const int bm  = blockIdx.x * BM;

    // ---- init: offset table, bias fold, barriers ----
    for (int k = t; k < DD; k += THREADS) {
        int c = k / 9, r = k - 9 * c;
        int i = r / 3, j = r - 3 * i;
        s_tab[k] = ((c * LL + i * HWD + j) << 4) | r;
    }
    if (t < COUT) s_ub[t] = fmaf(__ldg(&bias[t]), INV_PI, -0.25f);
    if (t == 0) {
        MBAR_INIT(bar_full[0], 128); MBAR_INIT(bar_full[1], 128);
        MBAR_INIT(bar_empty[0], 256); MBAR_INIT(bar_empty[1], 256);
    }
    __syncthreads();

    // consumer accumulators (declared here so epilogue can see them)
    float acc[4][4][4];
    const int wm = wid & 1;       // 0-1 : m offset 64*wm
    const int wn = wid >> 1;      // 0-3 : n offset 32*wn

    if (wid >= 8) {
        // =============== producers (128 threads) ===============
        const int pt   = t - 256;          // 0..127 = row within tile
        const int gm   = bm + pt;
        const int img  = gm / LL;
        const int l    = gm - img * LL;
        const int y    = l / HWD;
        const int xx   = l - y * HWD;
        const float* xp = x + (long)img * (CIN * LL) + y * HWD + xx - (HWD + 1);

        uint32_t vmask = 0;
        #pragma unroll
        for (int i = 0; i < 3; i++)
            #pragma unroll
            for (int j = 0; j < 3; j++)
                if (((unsigned)(y + i - 1) < HWD) && ((unsigned)(xx + j - 1) < HWD))
                    vmask |= 1u << (i * 3 + j);

        const uint32_t swm   = (uint32_t)((pt & 7) << 4);
        const long     wrowB = (long)pt * DD;

        for (int c = 0; c < NCHUNK; c++) {
            const int s = c & 1;
            const int u = c >> 1;
            MBAR_WAIT(bar_empty[s], 1u ^ (u & 1));

            const uint32_t sb   = sbase + s * STAGE_B;
            const uint32_t arow = sb + pt * 128;
            const int kc = c * BK;

            // ---- A: im2col gather + 3-way bf16 split, row pt, 64 k ----
            #pragma unroll
            for (int g = 0; g < 8; g++) {
                uint32_t ph[4], pmv[4], plv[4];
                #pragma unroll
                for (int p = 0; p < 4; p++) {
                    int k  = kc + g * 8 + p * 2;
                    int e0 = s_tab[k], e1 = s_tab[k + 1];
                    float v0 = ((vmask >> (e0 & 15)) & 1) ? __ldg(xp + (e0 >> 4)) : 0.f;
                    float v1 = ((vmask >> (e1 & 15)) & 1) ? __ldg(xp + (e1 >> 4)) : 0.f;
                    __nv_bfloat162 h2 = __floats2bfloat162_rn(v0, v1);
                    float r0 = v0 - __bfloat162float(h2.x);
                    float r1 = v1 - __bfloat162float(h2.y);
                    __nv_bfloat162 m2 = __floats2bfloat162_rn(r0, r1);
                    float q0 = r0 - __bfloat162float(m2.x);
                    float q1 = r1 - __bfloat162float(m2.y);
                    __nv_bfloat162 l2 = __floats2bfloat162_rn(q0, q1);
                    ph[p]  = *(uint32_t*)&h2;
                    pmv[p] = *(uint32_t*)&m2;
                    plv[p] = *(uint32_t*)&l2;
                }
                uint32_t off = ((uint32_t)(g * 16)) ^ swm;
                uint4 vh = make_uint4(ph[0], ph[1], ph[2], ph[3]);
                uint4 vm = make_uint4(pmv[0], pmv[1], pmv[2], pmv[3]);
                uint4 vl = make_uint4(plv[0], plv[1], plv[2], plv[3]);
                STS128(arow + 0 * TILE_B + off, vh);
                STS128(arow + 1 * TILE_B + off, vm);
                STS128(arow + 2 * TILE_B + off, vl);
            }

            // ---- B: copy pre-split weights, row pt, 64 k ----
            {
                const uint32_t brow = sb + 3 * TILE_B + pt * 128;
                const uint4* sH = (const uint4*)(g_Wh + wrowB + kc);
                const uint4* sM = (const uint4*)(g_Wm + wrowB + kc);
                const uint4* sL = (const uint4*)(g_Wl + wrowB + kc);
                #pragma unroll
                for (int q = 0; q < 8; q++) {
                    uint32_t off = ((uint32_t)(q * 16)) ^ swm;
                    uint4 vh = __ldg(&sH[q]);
                    uint4 vm = __ldg(&sM[q]);
                    uint4 vl = __ldg(&sL[q]);
                    STS128(brow + 0 * TILE_B + off, vh);
                    STS128(brow + 1 * TILE_B + off, vm);
                    STS128(brow + 2 * TILE_B + off, vl);
                }
            }
            MBAR_ARRIVE(bar_full[s]);
        }
    } else {
        // =============== consumers (256 threads, 8 warps) ===============
        #pragma unroll
        for (int i = 0; i < 4; i++)
            #pragma unroll
            for (int j = 0; j < 4; j++)
                #pragma unroll
                for (int e = 0; e < 4; e++) acc[i][j][e] = 0.f;

        // ldmatrix lane-derived address components
        const int rA = lid & 15;
        const int kAl = (lid >> 4) * 16;
        const uint32_t swA = (uint32_t)((rA & 7) << 4);
        const uint32_t byA = (uint32_t)(rA * 128);
        const int rB = (lid & 7) + ((lid >> 4) << 3);
        const int kBl = ((lid >> 3) & 1) * 16;
        const uint32_t swB = (uint32_t)((lid & 7) << 4);
        const uint32_t byB = (uint32_t)(rB * 128);

        const uint32_t mbase = (uint32_t)(wm * 64 * 128);   // byte offset of warp m-rows
        const uint32_t nbase = (uint32_t)(wn * 32 * 128);   // byte offset of warp n-rows

        for (int c = 0; c < NCHUNK; c++) {
            const int s = c & 1;
            const int u = c >> 1;
            MBAR_WAIT(bar_full[s], (u & 1));

            const uint32_t sb  = sbase + s * STAGE_B;
            const uint32_t pAh = sb + 0 * TILE_B + mbase + byA;
            const uint32_t pAm = sb + 1 * TILE_B + mbase + byA;
            const uint32_t pAl = sb + 2 * TILE_B + mbase + byA;
            const uint32_t pBh = sb + 3 * TILE_B + nbase + byB;
            const uint32_t pBm = sb + 4 * TILE_B + nbase + byB;
            const uint32_t pBl = sb + 5 * TILE_B + nbase + byB;

            // m-half split so the zeroed temp fits registers (2 mf x 4 nf x 4)
            #pragma unroll
            for (int mh = 0; mh < 2; mh++) {
                float tmp[2][4][4];
                #pragma unroll
                for (int i = 0; i < 2; i++)
                    #pragma unroll
                    for (int j = 0; j < 4; j++)
                        #pragma unroll
                        for (int e = 0; e < 4; e++) tmp[i][j][e] = 0.f;

                #pragma unroll
                for (int ks = 0; ks < 4; ks++) {
                    const uint32_t aoff = (uint32_t)((ks * 32 + kAl)) ^ swA;
                    const uint32_t boff = (uint32_t)((ks * 32 + kBl)) ^ swB;

                    uint32_t Ah[2][4], Am[2][4], Al[2][4];
                    uint32_t Bh[2][4], Bm[2][4], Bl[2][4];
                    #pragma unroll
                    for (int mf = 0; mf < 2; mf++) {
                        const uint32_t ro = (uint32_t)((mh * 2 + mf) * (16 * 128));
                        LDSM4(Ah[mf], pAh + ro + aoff);
                        LDSM4(Am[mf], pAm + ro + aoff);
                        LDSM4(Al[mf], pAl + ro + aoff);
                    }
                    #pragma unroll
                    for (int g = 0; g < 2; g++) {
                        const uint32_t go = (uint32_t)(g * (16 * 128));
                        LDSM4(Bh[g], pBh + go + boff);
                        LDSM4(Bm[g], pBm + go + boff);
                        LDSM4(Bl[g], pBl + go + boff);
                    }

                    // small terms first, hh last (minimize truncation vs |tmp|)
                    #pragma unroll
                    for (int mf = 0; mf < 2; mf++)
                        #pragma unroll
                        for (int g = 0; g < 2; g++) {
                            float* t0 = tmp[mf][g * 2 + 0];
                            float* t1 = tmp[mf][g * 2 + 1];
                            MMA(t0, Al[mf], Bh[g][0], Bh[g][1]);   // lh
                            MMA(t1, Al[mf], Bh[g][2], Bh[g][3]);
                            MMA(t0, Am[mf], Bm[g][0], Bm[g][1]);   // mm
                            MMA(t1, Am[mf], Bm[g][2], Bm[g][3]);
                            MMA(t0, Ah[mf], Bl[g][0], Bl[g][1]);   // hl
                            MMA(t1, Ah[mf], Bl[g][2], Bl[g][3]);
                            MMA(t0, Am[mf], Bh[g][0], Bh[g][1]);   // mh
                            MMA(t1, Am[mf], Bh[g][2], Bh[g][3]);
                            MMA(t0, Ah[mf], Bm[g][0], Bm[g][1]);   // hm
                            MMA(t1, Ah[mf], Bm[g][2], Bm[g][3]);
                            MMA(t0, Ah[mf], Bh[g][0], Bh[g][1]);   // hh
                            MMA(t1, Ah[mf], Bh[g][2], Bh[g][3]);
                        }

                    // fold every K=32 (two k-steps) into main acc with RN adds
                    if (ks & 1) {
                        #pragma unroll
                        for (int mf = 0; mf < 2; mf++)
                            #pragma unroll
                            for (int nf = 0; nf < 4; nf++)
                                #pragma unroll
                                for (int e = 0; e < 4; e++) {
                                    acc[mh * 2 + mf][nf][e] += tmp[mf][nf][e];
                                    tmp[mf][nf][e] = 0.f;
                                }
                    }
                }
            }
            MBAR_ARRIVE(bar_empty[s]);
        }
    }

    __syncthreads();

    // =============== epilogue: smem transpose + binarize + store ===============
    float* scratch = (float*)dsm;          // [128 n][132 m] fp32 (reuses stage mem)
    if (wid < 8) {
        #pragma unroll
        for (int mf = 0; mf < 4; mf++) {
            const int m = wm * 64 + mf * 16 + (lid >> 2);
            #pragma unroll
            for (int nf = 0; nf < 4; nf++) {
                const int n = wn * 32 + nf * 8 + 2 * (lid & 3);
                scratch[n * 132 + m]           = acc[mf][nf][0];
                scratch[(n + 1) * 132 + m]     = acc[mf][nf][1];
                scratch[n * 132 + m + 8]       = acc[mf][nf][2];
                scratch[(n + 1) * 132 + m + 8] = acc[mf][nf][3];
            }
        }
    }
    __syncthreads();

    for (int i = t; i < COUT * 32; i += THREADS) {
        const int n  = i >> 5;
        const int mq = i & 31;
        float4 v = *(const float4*)&scratch[n * 132 + mq * 4];
        const int gm  = bm + mq * 4;
        const int img = gm / LL;
        const int l0  = gm - img * LL;
        const float ub = s_ub[n];
        float4 o;
        {
            float u0 = fmaf(v.x, INV_PI, ub); float f0 = u0 - floorf(u0); o.x = (f0 < 0.5f) ? 1.f : 0.f;
            float u1 = fmaf(v.y, INV_PI, ub); float f1 = u1 - floorf(u1); o.y = (f1 < 0.5f) ? 1.f : 0.f;
            float u2 = fmaf(v.z, INV_PI, ub); float f2 = u2 - floorf(u2); o.z = (f2 < 0.5f) ? 1.f : 0.f;
            float u3 = fmaf(v.w, INV_PI, ub); float f3 = u3 - floorf(u3); o.w = (f3 < 0.5f) ? 1.f : 0.f;
        }
        *(float4*)&out[((size_t)img * COUT + n) * LL + l0] = o;
    }
}

extern "C" void kernel_launch(void* const* d_in, const int* in_sizes, int n_in,
                              void* d_out, int out_size) {
    const float* x = (const float*)d_in[0];   // (32, 64, 56, 56)
    const float* W = (const float*)d_in[1];   // (128, 576)
    const float* b = (const float*)d_in[2];   // (128,)
    float* out = (float*)d_out;               // (32, 128, 56, 56)

    cudaFuncSetAttribute(conv_mma_kernel,
                         cudaFuncAttributeMaxDynamicSharedMemorySize, SMEM_DYN);

    split_w_kernel<<<(COUT * DD + 255) / 256, 256>>>(W);
    conv_mma_kernel<<<MM / BM, THREADS, SMEM_DYN>>>(x, b, out);
}

// round 7
// speedup vs baseline: 1.1894x; 1.0033x over previous
#include <cuda_runtime.h>
#include <cuda_bf16.h>
#include <stdint.h>
#include <math.h>

// Problem constants
#define CIN    64
#define HWD    56
#define LL     3136
#define COUT   128
#define MM     100352
#define DD     576
#define BM     128
#define BK     64
#define NCHUNK 9
#define THREADS 384          // warps 0-7 consumers, 8-11 producers
#define INV_PI 0.3183098861837907f

// 3-way bf16 split of W, [COUT][DD] (k-contiguous = exactly what ldmatrix B wants)
__device__ __nv_bfloat16 g_Wh[COUT*DD];
__device__ __nv_bfloat16 g_Wm[COUT*DD];
__device__ __nv_bfloat16 g_Wl[COUT*DD];

__global__ void split_w_kernel(const float* __restrict__ W) {
    int i = blockIdx.x * 256 + threadIdx.x;
    if (i < COUT * DD) {
        float v = W[i];
        __nv_bfloat16 h = __float2bfloat16(v);
        float r1 = v - __bfloat162float(h);
        __nv_bfloat16 m = __float2bfloat16(r1);
        float r2 = r1 - __bfloat162float(m);
        g_Wh[i] = h; g_Wm[i] = m; g_Wl[i] = __float2bfloat16(r2);
    }
}

// ---------------- PTX helpers ----------------
__device__ __forceinline__ uint32_t smem_u32(const void* p) {
    uint32_t a;
    asm("{ .reg .u64 t; cvta.to.shared.u64 t, %1; cvt.u32.u64 %0, t; }" : "=r"(a) : "l"(p));
    return a;
}
#define MBAR_INIT(a, n) asm volatile("mbarrier.init.shared.b64 [%0], %1;" :: "r"(a), "r"(n) : "memory")
#define MBAR_ARRIVE(a)  asm volatile("mbarrier.arrive.shared.b64 _, [%0];" :: "r"(a) : "memory")
#define MBAR_WAIT(a, ph) do { \
    uint32_t _m = (a); uint32_t _p = (ph); uint32_t _d; \
    asm volatile("{\n\t.reg .pred p;\n\t" \
        "mbarrier.try_wait.parity.acquire.cta.shared::cta.b64 p, [%1], %2;\n\t" \
        "selp.b32 %0, 1, 0, p;\n\t}" : "=r"(_d) : "r"(_m), "r"(_p) : "memory"); \
    if (!_d) { \
        asm volatile("{\n\t.reg .pred P1;\n\t" \
            "WL_%=:\n\t" \
            "mbarrier.try_wait.parity.acquire.cta.shared::cta.b64 P1, [%0], %1, 0x989680;\n\t" \
            "@P1 bra.uni WD_%=;\n\t" \
            "bra.uni WL_%=;\n\t" \
            "WD_%=:\n\t}" :: "r"(_m), "r"(_p) : "memory"); \
    } } while (0)

#define STS128(a, v) asm volatile("st.shared.v4.b32 [%0], {%1,%2,%3,%4};" \
    :: "r"(a), "r"((v).x), "r"((v).y), "r"((v).z), "r"((v).w) : "memory")

#define LDSM4(r, a) asm volatile( \
    "ldmatrix.sync.aligned.m8n8.x4.shared.b16 {%0,%1,%2,%3}, [%4];" \
    : "=r"((r)[0]), "=r"((r)[1]), "=r"((r)[2]), "=r"((r)[3]) : "r"(a))

#define MMA(cc, a, b0_, b1_) asm volatile( \
    "mma.sync.aligned.m16n8k16.row.col.f32.bf16.bf16.f32 " \
    "{%0,%1,%2,%3},{%4,%5,%6,%7},{%8,%9},{%0,%1,%2,%3};" \
    : "+f"((cc)[0]), "+f"((cc)[1]), "+f"((cc)[2]), "+f"((cc)[3]) \
    : "r"((a)[0]), "r"((a)[1]), "r"((a)[2]), "r"((a)[3]), "r"(b0_), "r"(b1_))

// one split-term over all 8 independent accumulator chains (RAW spacing = 8 MMAs)
#define TERM(A_, B_) do { \
    _Pragma("unroll") \
    for (int mf_ = 0; mf_ < 2; mf_++) { \
        _Pragma("unroll") \
        for (int g_ = 0; g_ < 2; g_++) { \
            MMA(tmp[mf_][g_ * 2 + 0], A_[mf_], B_[g_][0], B_[g_][1]); \
            MMA(tmp[mf_][g_ * 2 + 1], A_[mf_], B_[g_][2], B_[g_][3]); \
        } \
    } } while (0)

// smem stage: 6 tiles (Ah Am Al Bh Bm Bl), each [128 rows][64 bf16 = 128B] swizzled
#define TILE_B  16384
#define STAGE_B (6 * TILE_B)
#define SMEM_DYN (2 * STAGE_B)

__global__ __launch_bounds__(THREADS, 1)
void conv_mma_kernel(const float* __restrict__ x,
                     const float* __restrict__ bias,
                     float* __restrict__ out) {
    extern __shared__ char dsm[];
    __shared__ __align__(8) unsigned long long s_bar[4]; // full0 full1 empty0 empty1
    __shared__ int   s_tab[DD];
    __shared__ float s_ub[COUT];

    const uint32_t sbase = smem_u32(dsm);
    const uint32_t bar_full[2]  = { smem_u32(&s_bar[0]), smem_u32(&s_bar[1]) };
    const uint32_t bar_empty[2] = { smem_u32(&s_bar[2]), smem_u32(&s_bar[3]) };

    const int t   = threadIdx.x;
    const int wid = t >> 5;
    const int lid = t & 31;
    const int bm  = blockIdx.x * BM;

    // ---- init: offset table, bias fold, barriers ----
    for (int k = t; k < DD; k += THREADS) {
        int c = k / 9, r = k - 9 * c;
        int i = r / 3, j = r - 3 * i;
        s_tab[k] = ((c * LL + i * HWD + j) << 4) | r;
    }
    if (t < COUT) s_ub[t] = fmaf(__ldg(&bias[t]), INV_PI, -0.25f);
    if (t == 0) {
        MBAR_INIT(bar_full[0], 128); MBAR_INIT(bar_full[1], 128);
        MBAR_INIT(bar_empty[0], 256); MBAR_INIT(bar_empty[1], 256);
    }
    __syncthreads();

    // consumer accumulators (declared here so epilogue can see them)
    float acc[4][4][4];
    const int wm = wid & 1;       // 0-1 : m offset 64*wm
    const int wn = wid >> 1;      // 0-3 : n offset 32*wn

    if (wid >= 8) {
        // =============== producers (128 threads) ===============
        const int pt   = t - 256;          // 0..127 = row within tile
        const int gm   = bm + pt;
        const int img  = gm / LL;
        const int l    = gm - img * LL;
        const int y    = l / HWD;
        const int xx   = l - y * HWD;
        const float* xp = x + (long)img * (CIN * LL) + y * HWD + xx - (HWD + 1);

        uint32_t vmask = 0;
        #pragma unroll
        for (int i = 0; i < 3; i++)
            #pragma unroll
            for (int j = 0; j < 3; j++)
                if (((unsigned)(y + i - 1) < HWD) && ((unsigned)(xx + j - 1) < HWD))
                    vmask |= 1u << (i * 3 + j);

        const uint32_t swm   = (uint32_t)((pt & 7) << 4);
        const long     wrowB = (long)pt * DD;

        for (int c = 0; c < NCHUNK; c++) {
            const int s = c & 1;
            const int u = c >> 1;
            MBAR_WAIT(bar_empty[s], 1u ^ (u & 1));

            const uint32_t sb   = sbase + s * STAGE_B;
            const uint32_t arow = sb + pt * 128;
            const int kc = c * BK;

            // ---- A: im2col gather + 3-way bf16 split, row pt, 64 k ----
            #pragma unroll
            for (int g = 0; g < 8; g++) {
                uint32_t ph[4], pmv[4], plv[4];
                #pragma unroll
                for (int p = 0; p < 4; p++) {
                    int k  = kc + g * 8 + p * 2;
                    int e0 = s_tab[k], e1 = s_tab[k + 1];
                    float v0 = ((vmask >> (e0 & 15)) & 1) ? __ldg(xp + (e0 >> 4)) : 0.f;
                    float v1 = ((vmask >> (e1 & 15)) & 1) ? __ldg(xp + (e1 >> 4)) : 0.f;
                    __nv_bfloat162 h2 = __floats2bfloat162_rn(v0, v1);
                    float r0 = v0 - __bfloat162float(h2.x);
                    float r1 = v1 - __bfloat162float(h2.y);
                    __nv_bfloat162 m2 = __floats2bfloat162_rn(r0, r1);
                    float q0 = r0 - __bfloat162float(m2.x);
                    float q1 = r1 - __bfloat162float(m2.y);
                    __nv_bfloat162 l2 = __floats2bfloat162_rn(q0, q1);
                    ph[p]  = *(uint32_t*)&h2;
                    pmv[p] = *(uint32_t*)&m2;
                    plv[p] = *(uint32_t*)&l2;
                }
                uint32_t off = ((uint32_t)(g * 16)) ^ swm;
                uint4 vh = make_uint4(ph[0], ph[1], ph[2], ph[3]);
                uint4 vm = make_uint4(pmv[0], pmv[1], pmv[2], pmv[3]);
                uint4 vl = make_uint4(plv[0], plv[1], plv[2], plv[3]);
                STS128(arow + 0 * TILE_B + off, vh);
                STS128(arow + 1 * TILE_B + off, vm);
                STS128(arow + 2 * TILE_B + off, vl);
            }

            // ---- B: copy pre-split weights, row pt, 64 k ----
            {
                const uint32_t brow = sb + 3 * TILE_B + pt * 128;
                const uint4* sH = (const uint4*)(g_Wh + wrowB + kc);
                const uint4* sM = (const uint4*)(g_Wm + wrowB + kc);
                const uint4* sL = (const uint4*)(g_Wl + wrowB + kc);
                #pragma unroll
                for (int q = 0; q < 8; q++) {
                    uint32_t off = ((uint32_t)(q * 16)) ^ swm;
                    uint4 vh = __ldg(&sH[q]);
                    uint4 vm = __ldg(&sM[q]);
                    uint4 vl = __ldg(&sL[q]);
                    STS128(brow + 0 * TILE_B + off, vh);
                    STS128(brow + 1 * TILE_B + off, vm);
                    STS128(brow + 2 * TILE_B + off, vl);
                }
            }
            MBAR_ARRIVE(bar_full[s]);
        }
    } else {
        // =============== consumers (256 threads, 8 warps) ===============
        #pragma unroll
        for (int i = 0; i < 4; i++)
            #pragma unroll
            for (int j = 0; j < 4; j++)
                #pragma unroll
                for (int e = 0; e < 4; e++) acc[i][j][e] = 0.f;

        // ldmatrix lane-derived address components
        const int rA = lid & 15;
        const int kAl = (lid >> 4) * 16;
        const uint32_t swA = (uint32_t)((rA & 7) << 4);
        const uint32_t byA = (uint32_t)(rA * 128);
        const int rB = (lid & 7) + ((lid >> 4) << 3);
        const int kBl = ((lid >> 3) & 1) * 16;
        const uint32_t swB = (uint32_t)((lid & 7) << 4);
        const uint32_t byB = (uint32_t)(rB * 128);

        const uint32_t mbase = (uint32_t)(wm * 64 * 128);   // byte offset of warp m-rows
        const uint32_t nbase = (uint32_t)(wn * 32 * 128);   // byte offset of warp n-rows

        for (int c = 0; c < NCHUNK; c++) {
            const int s = c & 1;
            const int u = c >> 1;
            MBAR_WAIT(bar_full[s], (u & 1));

            const uint32_t sb  = sbase + s * STAGE_B;
            const uint32_t pAh = sb + 0 * TILE_B + mbase + byA;
            const uint32_t pAm = sb + 1 * TILE_B + mbase + byA;
            const uint32_t pAl = sb + 2 * TILE_B + mbase + byA;
            const uint32_t pBh = sb + 3 * TILE_B + nbase + byB;
            const uint32_t pBm = sb + 4 * TILE_B + nbase + byB;
            const uint32_t pBl = sb + 5 * TILE_B + nbase + byB;

            #pragma unroll
            for (int ks = 0; ks < 4; ks++) {
                const uint32_t aoff = (uint32_t)((ks * 32 + kAl)) ^ swA;
                const uint32_t boff = (uint32_t)((ks * 32 + kBl)) ^ swB;

                // B frags loaded ONCE per ks (shared by both m-halves)
                uint32_t Bh[2][4], Bm[2][4], Bl[2][4];
                #pragma unroll
                for (int g = 0; g < 2; g++) {
                    const uint32_t go = (uint32_t)(g * (16 * 128));
                    LDSM4(Bh[g], pBh + go + boff);
                    LDSM4(Bm[g], pBm + go + boff);
                    LDSM4(Bl[g], pBl + go + boff);
                }

                #pragma unroll
                for (int mh = 0; mh < 2; mh++) {
                    uint32_t Ah[2][4], Am[2][4], Al[2][4];
                    #pragma unroll
                    for (int mf = 0; mf < 2; mf++) {
                        const uint32_t ro = (uint32_t)((mh * 2 + mf) * (16 * 128));
                        LDSM4(Ah[mf], pAh + ro + aoff);
                        LDSM4(Am[mf], pAm + ro + aoff);
                        LDSM4(Al[mf], pAl + ro + aoff);
                    }

                    // zeroed K=16 window accumulator (8 independent chains)
                    float tmp[2][4][4];
                    #pragma unroll
                    for (int i = 0; i < 2; i++)
                        #pragma unroll
                        for (int j = 0; j < 4; j++)
                            #pragma unroll
                            for (int e = 0; e < 4; e++) tmp[i][j][e] = 0.f;

                    // term-major: each chain touched once per 8 MMAs
                    TERM(Al, Bh);   // lh
                    TERM(Am, Bm);   // mm
                    TERM(Ah, Bl);   // hl
                    TERM(Am, Bh);   // mh
                    TERM(Ah, Bm);   // hm
                    TERM(Ah, Bh);   // hh
                    // fold window into main acc with RN adds
                    #pragma unroll
                    for (int mf = 0; mf < 2; mf++)
                        #pragma unroll
                        for (int nf = 0; nf < 4; nf++)
                            #pragma unroll
                            for (int e = 0; e < 4; e++)
                                acc[mh * 2 + mf][nf][e] += tmp[mf][nf][e];
                }
            }
            MBAR_ARRIVE(bar_empty[s]);
        }
    }

    __syncthreads();

    // =============== epilogue: smem transpose + binarize + store ===============
    float* scratch = (float*)dsm;          // [128 n][132 m] fp32 (reuses stage mem)
    if (wid < 8) {
        #pragma unroll
        for (int mf = 0; mf < 4; mf++) {
            const int m = wm * 64 + mf * 16 + (lid >> 2);
            #pragma unroll
            for (int nf = 0; nf < 4; nf++) {
                const int n = wn * 32 + nf * 8 + 2 * (lid & 3);
                scratch[n * 132 + m]           = acc[mf][nf][0];
                scratch[(n + 1) * 132 + m]     = acc[mf][nf][1];
                scratch[n * 132 + m + 8]       = acc[mf][nf][2];
                scratch[(n + 1) * 132 + m + 8] = acc[mf][nf][3];
            }
        }
    }
    __syncthreads();

    for (int i = t; i < COUT * 32; i += THREADS) {
        const int n  = i >> 5;
        const int mq = i & 31;
        float4 v = *(const float4*)&scratch[n * 132 + mq * 4];
        const int gm  = bm + mq * 4;
        const int img = gm / LL;
        const int l0  = gm - img * LL;
        const float ub = s_ub[n];
        float4 o;
        {
            float u0 = fmaf(v.x, INV_PI, ub); float f0 = u0 - floorf(u0); o.x = (f0 < 0.5f) ? 1.f : 0.f;
            float u1 = fmaf(v.y, INV_PI, ub); float f1 = u1 - floorf(u1); o.y = (f1 < 0.5f) ? 1.f : 0.f;
            float u2 = fmaf(v.z, INV_PI, ub); float f2 = u2 - floorf(u2); o.z = (f2 < 0.5f) ? 1.f : 0.f;
            float u3 = fmaf(v.w, INV_PI, ub); float f3 = u3 - floorf(u3); o.w = (f3 < 0.5f) ? 1.f : 0.f;
        }
        *(float4*)&out[((size_t)img * COUT + n) * LL + l0] = o;
    }
}

extern "C" void kernel_launch(void* const* d_in, const int* in_sizes, int n_in,
                              void* d_out, int out_size) {
    const float* x = (const float*)d_in[0];   // (32, 64, 56, 56)
    const float* W = (const float*)d_in[1];   // (128, 576)
    const float* b = (const float*)d_in[2];   // (128,)
    float* out = (float*)d_out;               // (32, 128, 56, 56)

    cudaFuncSetAttribute(conv_mma_kernel,
                         cudaFuncAttributeMaxDynamicSharedMemorySize, SMEM_DYN);

    split_w_kernel<<<(COUT * DD + 255) / 256, 256>>>(W);
    conv_mma_kernel<<<MM / BM, THREADS, SMEM_DYN>>>(x, b, out);
}